// round 15
// baseline (speedup 1.0000x reference)
#include <cuda_runtime.h>

namespace {

constexpr int Cc = 192;
constexpr int Hh = 128;
constexpr int Ww = 128;
constexpr int ROWS_PER_WARP = 4;
constexpr int WARPS = 2;
constexpr int THREADS = WARPS * 32;                     // 64
constexpr int ROWS_PER_BLOCK = WARPS * ROWS_PER_WARP;   // 8
constexpr int STRIPS_PER_PLANE = Hh / ROWS_PER_BLOCK;   // 16

__device__ __forceinline__ float tanh_approx(float t) {
    float r; asm("tanh.approx.f32 %0, %1;" : "=f"(r) : "f"(t)); return r;
}
// sigmoid(x*gw+gb) = 0.5*tanh((x*gw+gb)/2) + 0.5, with gw/2, gb/2 prefolded
__device__ __forceinline__ float gate_sig(float v, float a, float b) {
    return fmaf(tanh_approx(fmaf(v, a, b)), 0.5f, 0.5f);
}

// acc = max(acc, patch + t*k) over one input row (halo L/R), one kernel row
__device__ __forceinline__ void relax(float4& acc, const float4& t,
                                      float L, const float4& v, float R,
                                      float kl, float kc, float kr) {
    acc.x = fmaxf(acc.x, fmaf(t.x, kl, L));
    acc.x = fmaxf(acc.x, fmaf(t.x, kc, v.x));
    acc.x = fmaxf(acc.x, fmaf(t.x, kr, v.y));

    acc.y = fmaxf(acc.y, fmaf(t.y, kl, v.x));
    acc.y = fmaxf(acc.y, fmaf(t.y, kc, v.y));
    acc.y = fmaxf(acc.y, fmaf(t.y, kr, v.z));

    acc.z = fmaxf(acc.z, fmaf(t.z, kl, v.y));
    acc.z = fmaxf(acc.z, fmaf(t.z, kc, v.z));
    acc.z = fmaxf(acc.z, fmaf(t.z, kr, v.w));

    acc.w = fmaxf(acc.w, fmaf(t.w, kl, v.z));
    acc.w = fmaxf(acc.w, fmaf(t.w, kc, v.w));
    acc.w = fmaxf(acc.w, fmaf(t.w, kr, R));
}

// same but initializes acc (saves 4 FMNMX)
__device__ __forceinline__ void relax_init(float4& acc, const float4& t,
                                           float L, const float4& v, float R,
                                           float kl, float kc, float kr) {
    acc.x = fmaf(t.x, kc, v.x);
    acc.y = fmaf(t.y, kc, v.y);
    acc.z = fmaf(t.z, kc, v.z);
    acc.w = fmaf(t.w, kc, v.w);

    acc.x = fmaxf(acc.x, fmaf(t.x, kl, L));
    acc.x = fmaxf(acc.x, fmaf(t.x, kr, v.y));

    acc.y = fmaxf(acc.y, fmaf(t.y, kl, v.x));
    acc.y = fmaxf(acc.y, fmaf(t.y, kr, v.z));

    acc.z = fmaxf(acc.z, fmaf(t.z, kl, v.y));
    acc.z = fmaxf(acc.z, fmaf(t.z, kr, v.w));

    acc.w = fmaxf(acc.w, fmaf(t.w, kl, v.z));
    acc.w = fmaxf(acc.w, fmaf(t.w, kr, R));
}

__global__ void __launch_bounds__(THREADS, 26)
dynmorph_kernel(const float* __restrict__ x,
                const float* __restrict__ kern,
                const float* __restrict__ gw,
                const float* __restrict__ gb,
                float* __restrict__ out) {
    const int strip = blockIdx.x;
    const int plane = strip / STRIPS_PER_PLANE;
    const int part  = strip % STRIPS_PER_PLANE;
    const int c     = plane % Cc;
    const int warp  = threadIdx.x >> 5;
    const int lane  = threadIdx.x & 31;

    const float* __restrict__ xp = x   + (size_t)plane * (Hh * Ww);
    float*       __restrict__ op = out + (size_t)plane * (Hh * Ww);

    const float k0 = __ldg(&kern[c * 9 + 0]);
    const float k1 = __ldg(&kern[c * 9 + 1]);
    const float k2 = __ldg(&kern[c * 9 + 2]);
    const float k3 = __ldg(&kern[c * 9 + 3]);
    const float k4 = __ldg(&kern[c * 9 + 4]);
    const float k5 = __ldg(&kern[c * 9 + 5]);
    const float k6 = __ldg(&kern[c * 9 + 6]);
    const float k7 = __ldg(&kern[c * 9 + 7]);
    const float k8 = __ldg(&kern[c * 9 + 8]);
    // fold the /2 of the tanh-sigmoid identity into the gate params
    const float ga  = __ldg(&gw[c]) * 0.5f;
    const float gbp = __ldg(&gb[c]) * 0.5f;

    // edge masks: multiply instead of select (fma pipe vs alu pipe)
    const float edgeL = (lane == 0)  ? 0.f : 1.f;
    const float edgeR = (lane == 31) ? 0.f : 1.f;

    const int h0  = part * ROWS_PER_BLOCK + warp * ROWS_PER_WARP;
    const int col = lane * 4;

    const float* rowptr = xp + (size_t)h0 * Ww + col;
    float*       outptr = op + (size_t)h0 * Ww + col;

    float4 rm, r0, rp;
    float Lm, Rm, L0, R0, Lp, Rp;

    // row h0-1 (zero pad at top of plane; uniform branch per warp)
    if (h0 == 0) {
        rm = make_float4(0.f, 0.f, 0.f, 0.f);
    } else {
        rm = *reinterpret_cast<const float4*>(rowptr - Ww);
    }
    Lm = __shfl_up_sync(0xffffffffu, rm.w, 1) * edgeL;
    Rm = __shfl_down_sync(0xffffffffu, rm.x, 1) * edgeR;

    // row h0
    r0 = *reinterpret_cast<const float4*>(rowptr);
    L0 = __shfl_up_sync(0xffffffffu, r0.w, 1) * edgeL;
    R0 = __shfl_down_sync(0xffffffffu, r0.x, 1) * edgeR;

    // rr = 0..2: row h+1 = h0+rr+1 <= 127 always in-bounds -> branch-free.
#pragma unroll
    for (int rr = 0; rr < ROWS_PER_WARP - 1; rr++) {
        rp = *reinterpret_cast<const float4*>(rowptr + (size_t)(rr + 1) * Ww);
        Lp = __shfl_up_sync(0xffffffffu, rp.w, 1) * edgeL;
        Rp = __shfl_down_sync(0xffffffffu, rp.x, 1) * edgeR;

        float4 t;
        t.x = gate_sig(r0.x, ga, gbp);
        t.y = gate_sig(r0.y, ga, gbp);
        t.z = gate_sig(r0.z, ga, gbp);
        t.w = gate_sig(r0.w, ga, gbp);

        float4 acc;
        relax_init(acc, t, Lm, rm, Rm, k0, k1, k2);  // row h-1
        relax(acc, t, L0, r0, R0, k3, k4, k5);       // row h
        relax(acc, t, Lp, rp, Rp, k6, k7, k8);       // row h+1

        *reinterpret_cast<float4*>(outptr + (size_t)rr * Ww) = acc;

        rm = r0; Lm = L0; Rm = R0;
        r0 = rp; L0 = Lp; R0 = Rp;
    }

    // epilogue: last row of the strip; row h+1 may be the bottom pad
    {
        const int h = h0 + ROWS_PER_WARP - 1;
        if (h + 1 < Hh) {
            rp = *reinterpret_cast<const float4*>(rowptr + (size_t)ROWS_PER_WARP * Ww);
        } else {
            rp = make_float4(0.f, 0.f, 0.f, 0.f);
        }
        Lp = __shfl_up_sync(0xffffffffu, rp.w, 1) * edgeL;
        Rp = __shfl_down_sync(0xffffffffu, rp.x, 1) * edgeR;

        float4 t;
        t.x = gate_sig(r0.x, ga, gbp);
        t.y = gate_sig(r0.y, ga, gbp);
        t.z = gate_sig(r0.z, ga, gbp);
        t.w = gate_sig(r0.w, ga, gbp);

        float4 acc;
        relax_init(acc, t, Lm, rm, Rm, k0, k1, k2);
        relax(acc, t, L0, r0, R0, k3, k4, k5);
        relax(acc, t, Lp, rp, Rp, k6, k7, k8);

        *reinterpret_cast<float4*>(outptr + (size_t)(ROWS_PER_WARP - 1) * Ww) = acc;
    }
}

}  // namespace

extern "C" void kernel_launch(void* const* d_in, const int* in_sizes, int n_in,
                              void* d_out, int out_size) {
    const float* x    = (const float*)d_in[0];
    const float* kern = (const float*)d_in[1];
    const float* gw   = (const float*)d_in[2];
    const float* gb   = (const float*)d_in[3];
    float* out        = (float*)d_out;

    const int planes = in_sizes[0] / (Hh * Ww);  // B * C = 1536
    dynmorph_kernel<<<planes * STRIPS_PER_PLANE, THREADS>>>(x, kern, gw, gb, out);
}

// round 16
// speedup vs baseline: 1.0091x; 1.0091x over previous
#include <cuda_runtime.h>

namespace {

constexpr int Cc = 192;
constexpr int Hh = 128;
constexpr int Ww = 128;
constexpr int ROWS_PER_WARP = 4;
constexpr int WARPS = 2;
constexpr int THREADS = WARPS * 32;                     // 64
constexpr int ROWS_PER_BLOCK = WARPS * ROWS_PER_WARP;   // 8
constexpr int STRIPS_PER_PLANE = Hh / ROWS_PER_BLOCK;   // 16

__device__ __forceinline__ float tanh_approx(float t) {
    float r; asm("tanh.approx.f32 %0, %1;" : "=f"(r) : "f"(t)); return r;
}
// sigmoid(x*gw+gb) = 0.5*tanh((x*gw+gb)/2) + 0.5, with gw/2, gb/2 prefolded
__device__ __forceinline__ float gate_sig(float v, float a, float b) {
    return fmaf(tanh_approx(fmaf(v, a, b)), 0.5f, 0.5f);
}

// acc = max(acc, patch + t*k) over one input row (halo L/R), one kernel row
__device__ __forceinline__ void relax(float4& acc, const float4& t,
                                      float L, const float4& v, float R,
                                      float kl, float kc, float kr) {
    acc.x = fmaxf(acc.x, fmaf(t.x, kl, L));
    acc.x = fmaxf(acc.x, fmaf(t.x, kc, v.x));
    acc.x = fmaxf(acc.x, fmaf(t.x, kr, v.y));

    acc.y = fmaxf(acc.y, fmaf(t.y, kl, v.x));
    acc.y = fmaxf(acc.y, fmaf(t.y, kc, v.y));
    acc.y = fmaxf(acc.y, fmaf(t.y, kr, v.z));

    acc.z = fmaxf(acc.z, fmaf(t.z, kl, v.y));
    acc.z = fmaxf(acc.z, fmaf(t.z, kc, v.z));
    acc.z = fmaxf(acc.z, fmaf(t.z, kr, v.w));

    acc.w = fmaxf(acc.w, fmaf(t.w, kl, v.z));
    acc.w = fmaxf(acc.w, fmaf(t.w, kc, v.w));
    acc.w = fmaxf(acc.w, fmaf(t.w, kr, R));
}

// same but initializes acc (saves 4 FMNMX)
__device__ __forceinline__ void relax_init(float4& acc, const float4& t,
                                           float L, const float4& v, float R,
                                           float kl, float kc, float kr) {
    acc.x = fmaf(t.x, kc, v.x);
    acc.y = fmaf(t.y, kc, v.y);
    acc.z = fmaf(t.z, kc, v.z);
    acc.w = fmaf(t.w, kc, v.w);

    acc.x = fmaxf(acc.x, fmaf(t.x, kl, L));
    acc.x = fmaxf(acc.x, fmaf(t.x, kr, v.y));

    acc.y = fmaxf(acc.y, fmaf(t.y, kl, v.x));
    acc.y = fmaxf(acc.y, fmaf(t.y, kr, v.z));

    acc.z = fmaxf(acc.z, fmaf(t.z, kl, v.y));
    acc.z = fmaxf(acc.z, fmaf(t.z, kr, v.w));

    acc.w = fmaxf(acc.w, fmaf(t.w, kl, v.z));
    acc.w = fmaxf(acc.w, fmaf(t.w, kr, R));
}

__global__ void __launch_bounds__(THREADS, 32)
dynmorph_kernel(const float* __restrict__ x,
                const float* __restrict__ kern,
                const float* __restrict__ gw,
                const float* __restrict__ gb,
                float* __restrict__ out) {
    const int strip = blockIdx.x;
    const int plane = strip / STRIPS_PER_PLANE;
    const int part  = strip % STRIPS_PER_PLANE;
    const int c     = plane % Cc;
    const int warp  = threadIdx.x >> 5;
    const int lane  = threadIdx.x & 31;

    const float* __restrict__ xp = x   + (size_t)plane * (Hh * Ww);
    float*       __restrict__ op = out + (size_t)plane * (Hh * Ww);

    const float k0 = __ldg(&kern[c * 9 + 0]);
    const float k1 = __ldg(&kern[c * 9 + 1]);
    const float k2 = __ldg(&kern[c * 9 + 2]);
    const float k3 = __ldg(&kern[c * 9 + 3]);
    const float k4 = __ldg(&kern[c * 9 + 4]);
    const float k5 = __ldg(&kern[c * 9 + 5]);
    const float k6 = __ldg(&kern[c * 9 + 6]);
    const float k7 = __ldg(&kern[c * 9 + 7]);
    const float k8 = __ldg(&kern[c * 9 + 8]);
    // fold the /2 of the tanh-sigmoid identity into the gate params
    const float ga  = __ldg(&gw[c]) * 0.5f;
    const float gbp = __ldg(&gb[c]) * 0.5f;

    // edge masks: multiply instead of select (fma pipe vs alu pipe)
    const float edgeL = (lane == 0)  ? 0.f : 1.f;
    const float edgeR = (lane == 31) ? 0.f : 1.f;

    const int h0  = part * ROWS_PER_BLOCK + warp * ROWS_PER_WARP;
    const int col = lane * 4;

    const float* rowptr = xp + (size_t)h0 * Ww + col;
    float*       outptr = op + (size_t)h0 * Ww + col;

    float4 rm, r0, rp;
    float Lm, Rm, L0, R0, Lp, Rp;

    // row h0-1 (zero pad at top of plane; uniform branch per warp)
    if (h0 == 0) {
        rm = make_float4(0.f, 0.f, 0.f, 0.f);
    } else {
        rm = *reinterpret_cast<const float4*>(rowptr - Ww);
    }
    Lm = __shfl_up_sync(0xffffffffu, rm.w, 1) * edgeL;
    Rm = __shfl_down_sync(0xffffffffu, rm.x, 1) * edgeR;

    // row h0
    r0 = *reinterpret_cast<const float4*>(rowptr);
    L0 = __shfl_up_sync(0xffffffffu, r0.w, 1) * edgeL;
    R0 = __shfl_down_sync(0xffffffffu, r0.x, 1) * edgeR;

    // rr = 0..2: row h+1 = h0+rr+1 <= 127 always in-bounds -> branch-free.
#pragma unroll
    for (int rr = 0; rr < ROWS_PER_WARP - 1; rr++) {
        rp = *reinterpret_cast<const float4*>(rowptr + (size_t)(rr + 1) * Ww);
        Lp = __shfl_up_sync(0xffffffffu, rp.w, 1) * edgeL;
        Rp = __shfl_down_sync(0xffffffffu, rp.x, 1) * edgeR;

        float4 t;
        t.x = gate_sig(r0.x, ga, gbp);
        t.y = gate_sig(r0.y, ga, gbp);
        t.z = gate_sig(r0.z, ga, gbp);
        t.w = gate_sig(r0.w, ga, gbp);

        float4 acc;
        relax_init(acc, t, Lm, rm, Rm, k0, k1, k2);  // row h-1
        relax(acc, t, L0, r0, R0, k3, k4, k5);       // row h
        relax(acc, t, Lp, rp, Rp, k6, k7, k8);       // row h+1

        *reinterpret_cast<float4*>(outptr + (size_t)rr * Ww) = acc;

        rm = r0; Lm = L0; Rm = R0;
        r0 = rp; L0 = Lp; R0 = Rp;
    }

    // epilogue: last row of the strip; row h+1 may be the bottom pad
    {
        const int h = h0 + ROWS_PER_WARP - 1;
        if (h + 1 < Hh) {
            rp = *reinterpret_cast<const float4*>(rowptr + (size_t)ROWS_PER_WARP * Ww);
        } else {
            rp = make_float4(0.f, 0.f, 0.f, 0.f);
        }
        Lp = __shfl_up_sync(0xffffffffu, rp.w, 1) * edgeL;
        Rp = __shfl_down_sync(0xffffffffu, rp.x, 1) * edgeR;

        float4 t;
        t.x = gate_sig(r0.x, ga, gbp);
        t.y = gate_sig(r0.y, ga, gbp);
        t.z = gate_sig(r0.z, ga, gbp);
        t.w = gate_sig(r0.w, ga, gbp);

        float4 acc;
        relax_init(acc, t, Lm, rm, Rm, k0, k1, k2);
        relax(acc, t, L0, r0, R0, k3, k4, k5);
        relax(acc, t, Lp, rp, Rp, k6, k7, k8);

        *reinterpret_cast<float4*>(outptr + (size_t)(ROWS_PER_WARP - 1) * Ww) = acc;
    }
}

}  // namespace

extern "C" void kernel_launch(void* const* d_in, const int* in_sizes, int n_in,
                              void* d_out, int out_size) {
    const float* x    = (const float*)d_in[0];
    const float* kern = (const float*)d_in[1];
    const float* gw   = (const float*)d_in[2];
    const float* gb   = (const float*)d_in[3];
    float* out        = (float*)d_out;

    const int planes = in_sizes[0] / (Hh * Ww);  // B * C = 1536
    dynmorph_kernel<<<planes * STRIPS_PER_PLANE, THREADS>>>(x, kern, gw, gb, out);
}